// round 8
// baseline (speedup 1.0000x reference)
#include <cuda_runtime.h>
#include <cstdint>

#define Bz 64
#define Sz 512
#define Hz 1024
#define Tz 17
#define ROWS (Bz * Sz)   // 32768
#define WPAD 20          // padded row width for WshT (16B-aligned t-pairs)

// Static scratch (allocation-free): score history + backpointer table.
__device__ float g_score[Bz * Sz * Tz];          // 2.23 MB
__device__ unsigned char g_bp[Bz * Sz * Tz];     // 557 KB

// ---------------------------------------------------------------------------
// packed f32x2 helpers
// ---------------------------------------------------------------------------
__device__ __forceinline__ void fma2(unsigned long long& c,
                                     unsigned long long a,
                                     unsigned long long b) {
  asm("fma.rn.f32x2 %0, %1, %2, %0;" : "+l"(c) : "l"(a), "l"(b));
}
__device__ __forceinline__ unsigned long long dup2(float v) {
  unsigned long long r;
  asm("mov.b64 %0, {%1, %1};" : "=l"(r) : "r"(__float_as_uint(v)));
  return r;
}
__device__ __forceinline__ void unpack2(unsigned long long p, float& lo, float& hi) {
  unsigned int a, b;
  asm("mov.b64 {%0, %1}, %2;" : "=r"(a), "=r"(b) : "l"(p));
  lo = __uint_as_float(a); hi = __uint_as_float(b);
}

// ---------------------------------------------------------------------------
// Kernel 1: feats[r][t] = dot(x[r,:], W[t,:]) + b[t]
// W staged transposed [h][t] (pad 20) so t-pairs are contiguous -> one
// LDS.128 feeds two fma.rn.f32x2 operands. Accumulators packed over t-pairs;
// per-element arithmetic identical to scalar FFMA.
// ---------------------------------------------------------------------------
__global__ __launch_bounds__(256) void crf_gemm_kernel(
    const float* __restrict__ x, const float* __restrict__ W,
    const float* __restrict__ bias, float* __restrict__ feats) {
  __shared__ float WshT[512 * WPAD];  // 40960 B

  const int tid = threadIdx.x;
  const int warp = tid >> 5;
  const int lane = tid & 31;
  const int group = lane >> 2;
  const int sub = lane & 3;

  const int rowbase = blockIdx.x * 128 + warp * 16 + group * 2;
  const float* x0 = x + (size_t)rowbase * Hz;
  const float* x1 = x0 + Hz;

  unsigned long long ap0[8], ap1[8];  // t-pairs (0,1)..(14,15) for rows 0,1
  float a16_0 = 0.f, a16_1 = 0.f;     // t = 16
#pragma unroll
  for (int p = 0; p < 8; p++) { ap0[p] = 0ull; ap1[p] = 0ull; }

  for (int half = 0; half < 2; half++) {
    __syncthreads();
    // Stage transposed: WshT[hh*WPAD + t] = W[t*Hz + half*512 + hh]
#pragma unroll
    for (int t = 0; t < Tz; t++)
      for (int hh = tid; hh < 512; hh += 256)
        WshT[hh * WPAD + t] = W[t * Hz + half * 512 + hh];
    __syncthreads();

    const float* xh0 = x0 + half * 512;
    const float* xh1 = x1 + half * 512;
    for (int h0 = 0; h0 < 512; h0 += 16) {
      const int hb = h0 + sub * 4;
      const float4 xa = *(const float4*)(xh0 + hb);
      const float4 xb = *(const float4*)(xh1 + hb);
      const float xav[4] = {xa.x, xa.y, xa.z, xa.w};
      const float xbv[4] = {xb.x, xb.y, xb.z, xb.w};
#pragma unroll
      for (int i = 0; i < 4; i++) {
        const float* wrow = &WshT[(hb + i) * WPAD];
        const unsigned long long d0 = dup2(xav[i]);
        const unsigned long long d1 = dup2(xbv[i]);
#pragma unroll
        for (int k = 0; k < 4; k++) {
          const ulonglong2 w2 = *(const ulonglong2*)(wrow + 4 * k);
          fma2(ap0[2 * k], w2.x, d0);
          fma2(ap0[2 * k + 1], w2.y, d0);
          fma2(ap1[2 * k], w2.x, d1);
          fma2(ap1[2 * k + 1], w2.y, d1);
        }
        const float w16 = wrow[16];
        a16_0 = fmaf(xav[i], w16, a16_0);
        a16_1 = fmaf(xbv[i], w16, a16_1);
      }
    }
  }

  // Unpack to scalar accs, reduce across the 4 sub-lanes, store.
  float acc0[Tz], acc1[Tz];
#pragma unroll
  for (int p = 0; p < 8; p++) {
    unpack2(ap0[p], acc0[2 * p], acc0[2 * p + 1]);
    unpack2(ap1[p], acc1[2 * p], acc1[2 * p + 1]);
  }
  acc0[16] = a16_0; acc1[16] = a16_1;

#pragma unroll
  for (int t = 0; t < Tz; t++) {
    acc0[t] += __shfl_xor_sync(0xffffffffu, acc0[t], 1);
    acc0[t] += __shfl_xor_sync(0xffffffffu, acc0[t], 2);
    acc1[t] += __shfl_xor_sync(0xffffffffu, acc1[t], 1);
    acc1[t] += __shfl_xor_sync(0xffffffffu, acc1[t], 2);
  }
  if (sub == 0) {
#pragma unroll
    for (int t = 0; t < Tz; t++) {
      feats[(size_t)rowbase * Tz + t] = acc0[t] + bias[t];
      feats[(size_t)(rowbase + 1) * Tz + t] = acc1[t] + bias[t];
    }
  }
}

// ---------------------------------------------------------------------------
// max over 17 (tree, no index) and fused max+first-argmax tournament.
// Left bias (a >= b keeps left) == jnp.argmax first-max tie-break.
// ---------------------------------------------------------------------------
__device__ __forceinline__ float max17(const float* c) {
  float a = fmaxf(fmaxf(fmaxf(c[0], c[1]), fmaxf(c[2], c[3])),
                  fmaxf(fmaxf(c[4], c[5]), fmaxf(c[6], c[7])));
  float b = fmaxf(fmaxf(fmaxf(c[8], c[9]), fmaxf(c[10], c[11])),
                  fmaxf(fmaxf(c[12], c[13]), fmaxf(c[14], c[15])));
  return fmaxf(fmaxf(a, b), c[16]);
}

__device__ __forceinline__ void tourney17(const float* __restrict__ c,
                                          float& m, int& idx) {
  float v0[8]; int i0[8];
#pragma unroll
  for (int k = 0; k < 8; k++) {
    const float a = c[2 * k], b = c[2 * k + 1];
    v0[k] = fmaxf(a, b);
    i0[k] = (a >= b) ? (2 * k) : (2 * k + 1);
  }
  float v1[4]; int i1[4];
#pragma unroll
  for (int k = 0; k < 4; k++) {
    v1[k] = fmaxf(v0[2 * k], v0[2 * k + 1]);
    i1[k] = (v0[2 * k] >= v0[2 * k + 1]) ? i0[2 * k] : i0[2 * k + 1];
  }
  float v2[2]; int i2[2];
#pragma unroll
  for (int k = 0; k < 2; k++) {
    v2[k] = fmaxf(v1[2 * k], v1[2 * k + 1]);
    i2[k] = (v1[2 * k] >= v1[2 * k + 1]) ? i1[2 * k] : i1[2 * k + 1];
  }
  const float v3 = fmaxf(v2[0], v2[1]);
  const int i3 = (v2[0] >= v2[1]) ? i2[0] : i2[1];
  m = fmaxf(v3, c[16]);
  idx = (v3 >= c[16]) ? i3 : 16;
}

// ---------------------------------------------------------------------------
// Kernel 2: forward recurrence only (no argmax). Stores score rows 0..nw-1
// to g_score. Masked steps (s >= nw) are identity in the reference -> skipped.
// ---------------------------------------------------------------------------
__global__ __launch_bounds__(128) void crf_forward_kernel(
    const float* __restrict__ feats, const float* __restrict__ trans,
    const float* __restrict__ start_t, const int* __restrict__ nwords) {
  __shared__ float fsh[Sz * Tz];  // 34816 B

  const int b = blockIdx.x;
  const int tid = threadIdx.x;
  const float* fb = feats + (size_t)b * Sz * Tz;

  for (int i = tid * 4; i < Sz * Tz; i += 512)
    *(float4*)&fsh[i] = *(const float4*)&fb[i];

  const int nw = nwords[b];
  __syncthreads();

  if (tid < 32) {
    const int t = tid;
    const int tc = (t < Tz) ? t : (Tz - 1);
    float tcol[Tz];
#pragma unroll
    for (int j = 0; j < Tz; j++) tcol[j] = trans[j * Tz + tc];

    float score = start_t[tc] + fsh[tc];
    float* gs = g_score + (size_t)b * Sz * Tz;
    if (t < Tz) gs[t] = score;

    const float* frow = fsh + Tz;
    float* gsr = gs + Tz;
    for (int s = 1; s < nw; s++) {
      float c[Tz];
#pragma unroll
      for (int j = 0; j < Tz; j++)
        c[j] = __shfl_sync(0xffffffffu, score, j) + tcol[j];
      score = max17(c) + frow[tc];
      if (t < Tz) gsr[t] = score;
      frow += Tz;
      gsr += Tz;
    }
  }
}

// ---------------------------------------------------------------------------
// Kernel 3: backpointers, massively parallel over (b, s).
// bp[s][t] = argfirst_j(score[s-1][j] + trans[j][t]), for 1 <= s < nw.
// grid = (4, 64): blockIdx.y = batch, blockIdx.x = s-quarter. 4 warps/block.
// ---------------------------------------------------------------------------
__global__ __launch_bounds__(128) void crf_bp_kernel(
    const float* __restrict__ trans, const int* __restrict__ nwords) {
  const int b = blockIdx.y;
  const int q = blockIdx.x;
  const int tid = threadIdx.x;
  const int warp = tid >> 5;
  const int lane = tid & 31;
  const int tc = (lane < Tz) ? lane : (Tz - 1);

  const int nw = nwords[b];
  float tcol[Tz];
#pragma unroll
  for (int j = 0; j < Tz; j++) tcol[j] = trans[j * Tz + tc];

  const float* gs = g_score + (size_t)b * Sz * Tz;
  unsigned char* gb = g_bp + (size_t)b * Sz * Tz;

  const int sEnd0 = 1 + (q + 1) * 128;
  const int sEnd = (nw < sEnd0) ? nw : ((sEnd0 < Sz) ? sEnd0 : Sz);
  for (int s = 1 + q * 128 + warp; s < sEnd; s += 4) {
    const float sc = (lane < Tz) ? gs[(size_t)(s - 1) * Tz + lane] : 0.f;
    float c[Tz];
#pragma unroll
    for (int j = 0; j < Tz; j++)
      c[j] = __shfl_sync(0xffffffffu, sc, j) + tcol[j];
    float m; int bp;
    tourney17(c, m, bp);
    if (lane < Tz) gb[(size_t)s * Tz + lane] = (unsigned char)bp;
  }
}

// ---------------------------------------------------------------------------
// Kernel 4: backtrack chase per batch (bp table staged to smem) + tail zero.
// ---------------------------------------------------------------------------
__global__ __launch_bounds__(128) void crf_chase_kernel(
    const float* __restrict__ end_t, const int* __restrict__ nwords,
    float* __restrict__ tags_out) {
  __shared__ unsigned char bp_sh[Sz * Tz];  // 8704 B

  const int b = blockIdx.x;
  const int tid = threadIdx.x;
  const unsigned char* gb = g_bp + (size_t)b * Sz * Tz;

  for (int i = tid; i < (Sz * Tz) / 4; i += 128)
    ((unsigned int*)bp_sh)[i] = ((const unsigned int*)gb)[i];

  const int nw = nwords[b];
  __syncthreads();

  if (tid < 32) {
    const int t = tid;
    const int tc = (t < Tz) ? t : (Tz - 1);
    const float fin =
        g_score[(size_t)b * Sz * Tz + (size_t)(nw - 1) * Tz + tc] + end_t[tc];
    float fc[Tz];
#pragma unroll
    for (int j = 0; j < Tz; j++) fc[j] = __shfl_sync(0xffffffffu, fin, j);
    float fm; int last_tag;
    tourney17(fc, fm, last_tag);

    if (t == 0) {
      float* out = tags_out + (size_t)b * Sz;
      int tag = last_tag;
      out[nw - 1] = (float)tag;
      const unsigned char* bpr = bp_sh + (size_t)(nw - 1) * Tz;
      for (int s = nw - 1; s >= 1; s--) {
        tag = bpr[tag];
        bpr -= Tz;
        out[s - 1] = (float)tag;
      }
    }
  }

  for (int s = nw + tid; s < Sz; s += blockDim.x)
    tags_out[(size_t)b * Sz + s] = 0.0f;
}

// ---------------------------------------------------------------------------
// Inputs: x, W, b, transitions, start_trans, end_trans, nwords
// Output: [padded_tags (64*512) | feats (64*512*17)] as float32.
// ---------------------------------------------------------------------------
extern "C" void kernel_launch(void* const* d_in, const int* in_sizes, int n_in,
                              void* d_out, int out_size) {
  const float* x = (const float*)d_in[0];
  const float* W = (const float*)d_in[1];
  const float* bias = (const float*)d_in[2];
  const float* trans = (const float*)d_in[3];
  const float* start_t = (const float*)d_in[4];
  const float* end_t = (const float*)d_in[5];
  const int* nwords = (const int*)d_in[6];

  float* tags_out = (float*)d_out;
  float* feats = (float*)d_out + (size_t)Bz * Sz;

  crf_gemm_kernel<<<ROWS / 128, 256>>>(x, W, bias, feats);
  crf_forward_kernel<<<Bz, 128>>>(feats, trans, start_t, nwords);
  crf_bp_kernel<<<dim3(4, Bz), 128>>>(trans, nwords);
  crf_chase_kernel<<<Bz, 128>>>(end_t, nwords, tags_out);
}

// round 9
// speedup vs baseline: 2.0778x; 2.0778x over previous
#include <cuda_runtime.h>
#include <cstdint>

#define Bz 64
#define Sz 512
#define Hz 1024
#define Tz 17
#define ROWS (Bz * Sz)   // 32768

// ---------------------------------------------------------------------------
// Kernel 1: feats[r][t] = dot(x[r,:], W[t,:]) + b[t]
// R1 version, measured 53.8us. Block: 256 threads (8 warps). Warp handles 16
// rows: lane l -> row pair (2*(l/4), +1), sub = l%4 covers 4 h each per 16-h
// step. W staged in static shared in two 512-h halves so x is read once.
// ---------------------------------------------------------------------------
__global__ __launch_bounds__(256) void crf_gemm_kernel(
    const float* __restrict__ x, const float* __restrict__ W,
    const float* __restrict__ bias, float* __restrict__ feats) {
  __shared__ float Wsh[Tz * 512];  // 34816 B

  const int tid = threadIdx.x;
  const int warp = tid >> 5;
  const int lane = tid & 31;
  const int group = lane >> 2;
  const int sub = lane & 3;

  const int rowbase = blockIdx.x * 128 + warp * 16 + group * 2;
  const float* x0 = x + (size_t)rowbase * Hz;
  const float* x1 = x0 + Hz;

  float acc0[Tz], acc1[Tz];
#pragma unroll
  for (int t = 0; t < Tz; t++) { acc0[t] = 0.f; acc1[t] = 0.f; }

  for (int half = 0; half < 2; half++) {
    __syncthreads();
    for (int i = tid * 4; i < Tz * 512; i += 1024) {
      int t = i >> 9;
      int hh = i & 511;
      *(float4*)&Wsh[i] = *(const float4*)&W[t * Hz + half * 512 + hh];
    }
    __syncthreads();

    const float* xh0 = x0 + half * 512;
    const float* xh1 = x1 + half * 512;
#pragma unroll 2
    for (int h0 = 0; h0 < 512; h0 += 16) {
      const int h = h0 + sub * 4;
      const float4 xa = *(const float4*)(xh0 + h);
      const float4 xb = *(const float4*)(xh1 + h);
#pragma unroll
      for (int t = 0; t < Tz; t++) {
        const float4 wv = *(const float4*)&Wsh[t * 512 + h];
        acc0[t] += xa.x * wv.x + xa.y * wv.y + xa.z * wv.z + xa.w * wv.w;
        acc1[t] += xb.x * wv.x + xb.y * wv.y + xb.z * wv.z + xb.w * wv.w;
      }
    }
  }

#pragma unroll
  for (int t = 0; t < Tz; t++) {
    acc0[t] += __shfl_xor_sync(0xffffffffu, acc0[t], 1);
    acc0[t] += __shfl_xor_sync(0xffffffffu, acc0[t], 2);
    acc1[t] += __shfl_xor_sync(0xffffffffu, acc1[t], 1);
    acc1[t] += __shfl_xor_sync(0xffffffffu, acc1[t], 2);
  }
  if (sub == 0) {
#pragma unroll
    for (int t = 0; t < Tz; t++) {
      feats[(size_t)rowbase * Tz + t] = acc0[t] + bias[t];
      feats[(size_t)(rowbase + 1) * Tz + t] = acc1[t] + bias[t];
    }
  }
}

// ---------------------------------------------------------------------------
// Fused max + first-argmax over 17 values, depth-5 left-biased tournament.
// Left bias (a >= b keeps left) == jnp.argmax first-max tie-break, because
// every tree level pairs (lower indices, higher indices) in index order.
// ---------------------------------------------------------------------------
__device__ __forceinline__ void tourney17(const float* __restrict__ c,
                                          float& m, int& idx) {
  float v0[8]; int i0[8];
#pragma unroll
  for (int k = 0; k < 8; k++) {
    const float a = c[2 * k], b = c[2 * k + 1];
    v0[k] = fmaxf(a, b);
    i0[k] = (a >= b) ? (2 * k) : (2 * k + 1);
  }
  float v1[4]; int i1[4];
#pragma unroll
  for (int k = 0; k < 4; k++) {
    v1[k] = fmaxf(v0[2 * k], v0[2 * k + 1]);
    i1[k] = (v0[2 * k] >= v0[2 * k + 1]) ? i0[2 * k] : i0[2 * k + 1];
  }
  float v2[2]; int i2[2];
#pragma unroll
  for (int k = 0; k < 2; k++) {
    v2[k] = fmaxf(v1[2 * k], v1[2 * k + 1]);
    i2[k] = (v1[2 * k] >= v1[2 * k + 1]) ? i1[2 * k] : i1[2 * k + 1];
  }
  const float v3 = fmaxf(v2[0], v2[1]);
  const int i3 = (v2[0] >= v2[1]) ? i2[0] : i2[1];
  m = fmaxf(v3, c[16]);
  idx = (v3 >= c[16]) ? i3 : 16;
}

// ---------------------------------------------------------------------------
// Kernel 2: Viterbi, monolithic. 64 blocks; warp 0 runs the recurrence,
// lane t owns tag t. Only steps s = 1..nwords-1 run (masked steps are
// identity in the reference; padded tags are zeroed anyway).
// ---------------------------------------------------------------------------
__global__ __launch_bounds__(128) void crf_viterbi_kernel(
    const float* __restrict__ feats, const float* __restrict__ trans,
    const float* __restrict__ start_t, const float* __restrict__ end_t,
    const int* __restrict__ nwords, float* __restrict__ tags_out) {
  __shared__ float fsh[Sz * Tz];           // 34816 B
  __shared__ unsigned char bp_sh[Sz * Tz]; // 8704 B

  const int b = blockIdx.x;
  const int tid = threadIdx.x;
  const float* fb = feats + (size_t)b * Sz * Tz;

  for (int i = tid * 4; i < Sz * Tz; i += 512)
    *(float4*)&fsh[i] = *(const float4*)&fb[i];

  const int nw = nwords[b];
  __syncthreads();

  if (tid < 32) {
    const int t = tid;
    const int tc = (t < Tz) ? t : (Tz - 1);
    float tcol[Tz];
#pragma unroll
    for (int j = 0; j < Tz; j++) tcol[j] = trans[j * Tz + tc];

    float score = start_t[tc] + fsh[tc];
    const float* frow = fsh + Tz;
    unsigned char* bprow = bp_sh + Tz;

    for (int s = 1; s < nw; s++) {
      float c[Tz];
#pragma unroll
      for (int j = 0; j < Tz; j++)
        c[j] = __shfl_sync(0xffffffffu, score, j) + tcol[j];
      float m; int bp;
      tourney17(c, m, bp);
      score = m + frow[tc];
      if (t < Tz) bprow[t] = (unsigned char)bp;
      frow += Tz;
      bprow += Tz;
    }

    const float fin = score + end_t[tc];
    float fc[Tz];
#pragma unroll
    for (int j = 0; j < Tz; j++) fc[j] = __shfl_sync(0xffffffffu, fin, j);
    float fm; int last_tag;
    tourney17(fc, fm, last_tag);

    if (t == 0) {
      float* out = tags_out + (size_t)b * Sz;
      int tag = last_tag;
      out[nw - 1] = (float)tag;
      const unsigned char* bpr = bp_sh + (size_t)(nw - 1) * Tz;
      for (int s = nw - 1; s >= 1; s--) {
        tag = bpr[tag];
        bpr -= Tz;
        out[s - 1] = (float)tag;
      }
    }
  }

  // Zero the masked tail (disjoint from backtrack writes).
  for (int s = nw + tid; s < Sz; s += blockDim.x)
    tags_out[(size_t)b * Sz + s] = 0.0f;
}

// ---------------------------------------------------------------------------
// Inputs: x, W, b, transitions, start_trans, end_trans, nwords
// Output: [padded_tags (64*512) | feats (64*512*17)] as float32.
// ---------------------------------------------------------------------------
extern "C" void kernel_launch(void* const* d_in, const int* in_sizes, int n_in,
                              void* d_out, int out_size) {
  const float* x = (const float*)d_in[0];
  const float* W = (const float*)d_in[1];
  const float* bias = (const float*)d_in[2];
  const float* trans = (const float*)d_in[3];
  const float* start_t = (const float*)d_in[4];
  const float* end_t = (const float*)d_in[5];
  const int* nwords = (const int*)d_in[6];

  float* tags_out = (float*)d_out;
  float* feats = (float*)d_out + (size_t)Bz * Sz;

  crf_gemm_kernel<<<ROWS / 128, 256>>>(x, W, bias, feats);
  crf_viterbi_kernel<<<Bz, 128>>>(feats, trans, start_t, end_t, nwords, tags_out);
}